// round 7
// baseline (speedup 1.0000x reference)
#include <cuda_runtime.h>
#include <math.h>

#define N_ 2048
#define E_ 65536
#define D_ 512

#define MB_ 64                  // persistent blocks
#define MT_ 512                 // threads/block
#define NT_ (MB_ * MT_)         // 32768 threads; 1024 warps; 2 nodes/warp; 2 edges/thread

// ---------------- static device scratch (no allocations allowed) ----------------
__device__ int   g_degin[N_], g_degout[N_];
__device__ int   g_rpin[N_ + 1], g_rpout[N_ + 1];
__device__ int   g_curin[N_], g_curout[N_];
__device__ int   g_cscsrc[E_];        // CSC: senders grouped by receiver
__device__ int   g_csrdst[E_];        // CSR: dst grouped by src
__device__ float g_csrw[E_];          // prescaled 0.5*w/s_row
__device__ float g_s[N_], g_invs[N_], g_dd[N_], g_diag[N_];
__device__ int   g_a[N_], g_bb[N_], g_mka[N_], g_mkb[N_];
__device__ int   g_qlist[N_], g_colmap[N_];
__device__ int   g_M;
__device__ int   g_cluster[N_];       // cluster id (original node index q)
__device__ int   g_clustc[N_];        // compact cluster index (M = fallback)
__device__ int   g_counts[N_];
// barrier words on SEPARATE 128B lines: [0]=cnt, [32]=release, [64],[65]=strag
__device__ unsigned g_bar[96];
__device__ float g_B[(size_t)N_ * N_]; // compact rw[:, MIS] (stride = M)

__device__ __forceinline__ int ldvi(const int* p) { return *(const volatile int*)p; }

// ---------------- per-replay init ----------------
__global__ void k_init()
{
    int i = blockIdx.x * blockDim.x + threadIdx.x;
    if (i < N_) { g_degin[i] = 0; g_degout[i] = 0; g_s[i] = 0.f; g_diag[i] = 0.f; g_counts[i] = 0; }
    if (i < 96) g_bar[i] = 0u;
}

// ---------------- grid barrier (split lines) ----------------
__device__ __forceinline__ void gridbar(unsigned& ph)
{
    __syncthreads();
    if (threadIdx.x == 0) {
        __threadfence();
        unsigned a = atomicAdd(&g_bar[0], 1u);
        unsigned rel = 2u * (ph + 1u);
        if (a + 1u == (ph + 1u) * (unsigned)MB_) {
            *((volatile unsigned*)&g_bar[32]) = rel;
        } else {
            while (*((volatile unsigned*)&g_bar[32]) < rel) {}
        }
        __threadfence();
    }
    ph++;
    __syncthreads();
}

// ================= THE fused persistent kernel =================
__global__ void __launch_bounds__(MT_, 1)
k_all(const int* __restrict__ ei, const float* __restrict__ ea,
      const float* __restrict__ x, const int* __restrict__ rank,
      const float* __restrict__ u, float* __restrict__ out, int out_size)
{
    const int bid  = blockIdx.x;
    const int t    = threadIdx.x;
    const int tid  = bid * MT_ + t;
    const int lane = tid & 31;
    const int wid  = tid >> 5;            // global warp id 0..1023

    __shared__ int sMem[2 * N_];
    __shared__ int sFlag;
    int* sA = sMem;
    int* sB = sMem + N_;

    size_t nn = (size_t)N_ * N_;
    float* adjc  = out;
    float* chard = out + nn;
    float* pinv  = out + 2 * nn;
    float* miso  = out + 3 * nn;
    float* xpool = out + 3 * nn + N_;

    unsigned ph = 0;

    // two edges per thread, cached once
    const int   er0 = ei[tid],        ec0 = ei[E_ + tid];
    const int   er1 = ei[tid + NT_],  ec1 = ei[E_ + tid + NT_];
    const float ew0 = ea[tid],        ew1 = ea[tid + NT_];

    // ---- phase 1: degrees, row sums, diag ----
    atomicAdd(&g_degin[ec0], 1);  atomicAdd(&g_degin[ec1], 1);
    atomicAdd(&g_degout[er0], 1); atomicAdd(&g_degout[er1], 1);
    atomicAdd(&g_s[er0], ew0);    atomicAdd(&g_s[er1], ew1);
    if (er0 == ec0) atomicAdd(&g_diag[er0], ew0);
    if (er1 == ec1) atomicAdd(&g_diag[er1], ew1);
    gridbar(ph);

    // ---- phase 2: block0 scans rowptrs; others: invs/dd + output zero-fill ----
    if (bid == 0) {
        for (int pass = 0; pass < 2; pass++) {
            const int* src = pass ? g_degout : g_degin;
            int* rp  = pass ? g_rpout : g_rpin;
            int* cur = pass ? g_curout : g_curin;
            for (int i = t; i < N_; i += MT_) sA[i] = src[i];
            __syncthreads();
            int* in = sA; int* outp = sB;
            for (int off = 1; off < N_; off <<= 1) {
                for (int i = t; i < N_; i += MT_)
                    outp[i] = in[i] + (i >= off ? in[i - off] : 0);
                __syncthreads();
                int* tmp = in; in = outp; outp = tmp;
            }
            for (int i = t; i < N_; i += MT_) { rp[i + 1] = in[i]; cur[i] = i ? in[i - 1] : 0; }
            if (t == 0) rp[0] = 0;
            __syncthreads();
        }
    } else {
        int i = (bid - 1) * MT_ + t;
        if (i < N_) {
            float s = g_s[i];
            float inv = s > 0.f ? 1.f / s : 1.f;
            g_invs[i] = inv;
            g_dd[i] = 0.5f * (1.f + g_diag[i] * inv);
        }
        float4* o4 = (float4*)out;
        size_t tot4 = (size_t)out_size >> 2;
        for (size_t idx = (size_t)(bid - 1) * MT_ + t; idx < tot4; idx += (size_t)(MB_ - 1) * MT_)
            o4[idx] = make_float4(0.f, 0.f, 0.f, 0.f);
    }
    gridbar(ph);

    // ---- phase 3: fill CSC/CSR + init g_a (one barrier covers both) ----
    {
        int p0 = atomicAdd(&g_curin[ec0], 1); g_cscsrc[p0] = er0;
        int p1 = atomicAdd(&g_curin[ec1], 1); g_cscsrc[p1] = er1;
        int q0 = atomicAdd(&g_curout[er0], 1); g_csrdst[q0] = ec0; g_csrw[q0] = 0.5f * ew0 * g_invs[er0];
        int q1 = atomicAdd(&g_curout[er1], 1); g_csrdst[q1] = ec1; g_csrw[q1] = 0.5f * ew1 * g_invs[er1];
        if (tid < N_) g_a[tid] = rank[tid];
    }
    gridbar(ph);

    // ---- k-hop MIS: 2 nodes per warp, reg-cached in-lists, reg-carried state ----
    const int n0 = wid * 2, n1 = n0 + 1;
    const int beg0 = g_rpin[n0], end0 = g_rpin[n0 + 1];
    const int beg1 = g_rpin[n1], end1 = g_rpin[n1 + 1];
    const int src0 = (lane < end0 - beg0) ? g_cscsrc[beg0 + lane] : -1;
    const int src1 = (lane < end1 - beg1) ? g_cscsrc[beg1 + lane] : -1;
    const int rk0 = rank[n0], rk1 = rank[n1];
    int mis0 = 0, mis1 = 0;
    int a0 = rk0, a1 = rk1;

    for (int iter = 0; iter < N_; iter++) {
        // hop A: min-prop g_a -> g_bb
        int m10 = a0, m11 = a1;
        if (src0 >= 0) m10 = min(m10, ldvi(&g_a[src0]));
        if (src1 >= 0) m11 = min(m11, ldvi(&g_a[src1]));
        for (int e = beg0 + 32 + lane; e < end0; e += 32) m10 = min(m10, ldvi(&g_a[g_cscsrc[e]]));
        for (int e = beg1 + 32 + lane; e < end1; e += 32) m11 = min(m11, ldvi(&g_a[g_cscsrc[e]]));
        m10 = __reduce_min_sync(0xffffffffu, m10);
        m11 = __reduce_min_sync(0xffffffffu, m11);
        if (lane == 0) { g_bb[n0] = m10; g_bb[n1] = m11; }
        gridbar(ph);

        // hop B: min-prop g_bb -> local; mis update -> g_mka
        int m20 = m10, m21 = m11;
        if (src0 >= 0) m20 = min(m20, ldvi(&g_bb[src0]));
        if (src1 >= 0) m21 = min(m21, ldvi(&g_bb[src1]));
        for (int e = beg0 + 32 + lane; e < end0; e += 32) m20 = min(m20, ldvi(&g_bb[g_cscsrc[e]]));
        for (int e = beg1 + 32 + lane; e < end1; e += 32) m21 = min(m21, ldvi(&g_bb[g_cscsrc[e]]));
        m20 = __reduce_min_sync(0xffffffffu, m20);
        m21 = __reduce_min_sync(0xffffffffu, m21);
        mis0 |= (rk0 == m20) ? 1 : 0;
        mis1 |= (rk1 == m21) ? 1 : 0;
        if (lane == 0) { g_mka[n0] = mis0; g_mka[n1] = mis1; }
        gridbar(ph);

        // hop C: or-prop g_mka -> g_mkb
        int o10 = mis0, o11 = mis1;
        if (src0 >= 0) o10 = max(o10, ldvi(&g_mka[src0]));
        if (src1 >= 0) o11 = max(o11, ldvi(&g_mka[src1]));
        for (int e = beg0 + 32 + lane; e < end0; e += 32) o10 = max(o10, ldvi(&g_mka[g_cscsrc[e]]));
        for (int e = beg1 + 32 + lane; e < end1; e += 32) o11 = max(o11, ldvi(&g_mka[g_cscsrc[e]]));
        o10 = __reduce_max_sync(0xffffffffu, o10);
        o11 = __reduce_max_sync(0xffffffffu, o11);
        if (lane == 0) { g_mkb[n0] = o10; g_mkb[n1] = o11; }
        gridbar(ph);

        // hop D: or-prop g_mkb -> local; finalize; barrier with embedded flag
        int o20 = o10, o21 = o11;
        if (src0 >= 0) o20 = max(o20, ldvi(&g_mkb[src0]));
        if (src1 >= 0) o21 = max(o21, ldvi(&g_mkb[src1]));
        for (int e = beg0 + 32 + lane; e < end0; e += 32) o20 = max(o20, ldvi(&g_mkb[g_cscsrc[e]]));
        for (int e = beg1 + 32 + lane; e < end1; e += 32) o21 = max(o21, ldvi(&g_mkb[g_cscsrc[e]]));
        o20 = __reduce_max_sync(0xffffffffu, o20);
        o21 = __reduce_max_sync(0xffffffffu, o21);
        int mask0 = o20 > 0, mask1 = o21 > 0;
        a0 = mask0 ? N_ : rk0;
        a1 = mask1 ? N_ : rk1;
        if (lane == 0) { g_a[n0] = a0; g_a[n1] = a1; }
        int nm = (lane == 0 && (!mask0 || !mask1)) ? 1 : 0;
        int any = __syncthreads_count(nm);
        int parity = iter & 1;
        if (t == 0) {
            if (any) atomicAdd(&g_bar[64 + parity], 1u);
            __threadfence();
            unsigned a = atomicAdd(&g_bar[0], 1u);
            unsigned rel = 2u * (ph + 1u);
            unsigned flag;
            if (a + 1u == (ph + 1u) * (unsigned)MB_) {
                unsigned s = *((volatile unsigned*)&g_bar[64 + parity]);
                g_bar[64 + (parity ^ 1)] = 0u;
                flag = s ? 1u : 0u;
                __threadfence();
                *((volatile unsigned*)&g_bar[32]) = rel + flag;
            } else {
                unsigned v;
                while ((v = *((volatile unsigned*)&g_bar[32])) < rel) {}
                flag = v & 1u;
            }
            __threadfence();
            sFlag = (int)flag;
        }
        ph++;
        __syncthreads();
        if (sFlag == 0) break;
    }
    // g_mka now holds the final MIS (published >=2 barriers ago)

    // ---- compact (block 0) -> colmap/qlist/M ----
    if (bid == 0) {
        for (int i = t; i < N_; i += MT_) sA[i] = ldvi(&g_mka[i]);
        __syncthreads();
        int* in = sA; int* outp = sB;
        for (int off = 1; off < N_; off <<= 1) {
            for (int i = t; i < N_; i += MT_)
                outp[i] = in[i] + (i >= off ? in[i - off] : 0);
            __syncthreads();
            int* tmp = in; in = outp; outp = tmp;
        }
        for (int i = t; i < N_; i += MT_) {
            if (ldvi(&g_mka[i])) { int p = in[i] - 1; g_colmap[i] = p; g_qlist[p] = i; }
            else g_colmap[i] = -1;
        }
        if (t == 0) g_M = in[N_ - 1];
    }
    gridbar(ph);

    if (t == 0) sFlag = ldvi(&g_M);
    __syncthreads();
    const int M = sFlag;

    // ---- build B = rw[:, MIS]: warp-per-row, NO zeroing, NO atomics ----
    for (int rr = 0; rr < 2; rr++) {
        int r = n0 + rr;
        int rb = g_rpout[r], re2 = g_rpout[r + 1];
        int cmr = g_colmap[r];
        float ddr = g_dd[r];
        for (int m0 = 0; m0 < M; m0 += 32) {
            int m = m0 + lane;
            float acc = 0.f;
            for (int e = rb; e < re2; e++) {
                int cm = g_colmap[g_csrdst[e]];    // broadcast loads (uniform addr)
                float w = g_csrw[e];
                if (cm == m) acc += w;
            }
            if (cmr == m) acc += ddr;
            if (m < M) g_B[(size_t)r * M + m] = acc;
        }
    }
    gridbar(ph);

    // ---- SpMM c = rw @ B + fused Gumbel argmax + counts (2 rows per warp) ----
    for (int rr = 0; rr < 2; rr++) {
        int i = n0 + rr;
        int rb = g_rpout[i], re2 = g_rpout[i + 1];
        float dd = g_dd[i];
        const float* ui = u + (size_t)i * N_;
        float best = -INFINITY; int bq = 0x7FFFFFFF; int bm = 0;
        for (int m0 = 0; m0 < M; m0 += 32) {
            int m = m0 + lane;
            if (m < M) {
                float acc = dd * g_B[(size_t)i * M + m];
                for (int e = rb; e < re2; e++)
                    acc += g_csrw[e] * g_B[(size_t)g_csrdst[e] * M + m];
                if (acc > 0.f) {
                    int q = g_qlist[m];
                    float uu = ui[q];
                    float gum = -logf(-logf(uu + 1e-20f) + 1e-20f);
                    float lg = logf(fmaxf(acc, 1e-30f)) + gum;
                    if (lg > best || (lg == best && q < bq)) { best = lg; bq = q; bm = m; }
                }
            }
        }
        for (int o = 16; o > 0; o >>= 1) {
            float v  = __shfl_xor_sync(0xffffffffu, best, o);
            int   q  = __shfl_xor_sync(0xffffffffu, bq, o);
            int   mm = __shfl_xor_sync(0xffffffffu, bm, o);
            if (v > best || (v == best && q < bq)) { best = v; bq = q; bm = mm; }
        }
        if (lane == 0) {
            int cm, cl;
            if (bq == 0x7FFFFFFF) { cm = M; cl = 0; }
            else { cm = bm; cl = bq; }
            g_clustc[i]  = cm;
            g_cluster[i] = cl;
            atomicAdd(&g_counts[cl], 1);
        }
    }
    gridbar(ph);

    // ---- post: miso/chard/pinv + adj_c (smem-aggregated) + x_pool ----
    if (tid < N_) {
        int i = tid;
        miso[i] = g_mka[i] ? 1.f : 0.f;
        int c = g_cluster[i];
        chard[(size_t)i * N_ + c] = 1.f;
        pinv[(size_t)c * N_ + i] = 1.f / (float)g_counts[c];
    }

    {
        const int Mp1 = M + 1;
        if (Mp1 * Mp1 <= 2 * N_) {
            float* sbuf = (float*)sMem;
            for (int i2 = t; i2 < Mp1 * Mp1; i2 += MT_) sbuf[i2] = 0.f;
            __syncthreads();
            atomicAdd(&sbuf[g_clustc[er0] * Mp1 + g_clustc[ec0]], ew0);
            atomicAdd(&sbuf[g_clustc[er1] * Mp1 + g_clustc[ec1]], ew1);
            __syncthreads();
            for (int i2 = t; i2 < Mp1 * Mp1; i2 += MT_) {
                float v = sbuf[i2];
                if (v != 0.f) {
                    int m1 = i2 / Mp1, m2 = i2 % Mp1;
                    int r = (m1 < M) ? g_qlist[m1] : 0;
                    int c = (m2 < M) ? g_qlist[m2] : 0;
                    atomicAdd(&adjc[(size_t)r * N_ + c], v);
                }
            }
        } else {
            atomicAdd(&adjc[(size_t)g_cluster[er0] * N_ + g_cluster[ec0]], ew0);
            atomicAdd(&adjc[(size_t)g_cluster[er1] * N_ + g_cluster[ec1]], ew1);
        }
    }

    for (int idx = tid; idx < N_ * D_; idx += NT_) {
        int i = idx >> 9, d = idx & (D_ - 1);
        int c = g_cluster[i];
        float invc = 1.f / (float)g_counts[c];
        atomicAdd(&xpool[(size_t)c * D_ + d], x[idx] * invc);
    }
}

// ---------------- launch ----------------
extern "C" void kernel_launch(void* const* d_in, const int* in_sizes, int n_in,
                              void* d_out, int out_size)
{
    const int*   ei   = (const int*)d_in[0];     // edge_index [2, E]
    const float* ea   = (const float*)d_in[1];   // edge_attr  [E]
    const float* x    = (const float*)d_in[2];   // x          [N, D]
    const int*   rank = (const int*)d_in[3];     // rank       [N]
    const float* u    = (const float*)d_in[4];   // u          [N, N]

    (void)in_sizes; (void)n_in;

    k_init<<<8, 256>>>();
    k_all <<<MB_, MT_>>>(ei, ea, x, rank, u, (float*)d_out, out_size);
}

// round 8
// speedup vs baseline: 1.1941x; 1.1941x over previous
#include <cuda_runtime.h>
#include <math.h>

#define N_ 2048
#define E_ 65536
#define D_ 512

#define MB_ 128                 // persistent blocks (all co-resident on 148 SMs)
#define MT_ 512                 // threads/block
#define NT_ (MB_ * MT_)         // 65536 threads == E_; 2048 warps == N_ nodes

// ---------------- static device scratch (no allocations allowed) ----------------
__device__ int   g_degin[N_], g_degout[N_];
__device__ int   g_rpin[N_ + 1], g_rpout[N_ + 1];
__device__ int   g_curin[N_], g_curout[N_];
__device__ int   g_cscsrc[E_];        // CSC: senders grouped by receiver
__device__ int   g_csrdst[E_];        // CSR: dst grouped by src
__device__ float g_csrw[E_];          // prescaled 0.5*w/s_row
__device__ float g_s[N_], g_invs[N_], g_dd[N_], g_diag[N_];
__device__ int   g_a[N_], g_bb[N_], g_mka[N_], g_mkb[N_];
__device__ int   g_qlist[N_], g_colmap[N_];
__device__ int   g_M;
__device__ int   g_cluster[N_];       // cluster id (original node index q)
__device__ int   g_clustc[N_];        // compact cluster index (M = fallback)
__device__ int   g_counts[N_];
// barrier words on separate 128B lines: [0]=cnt, [32]=release, [64/65]=strag parity
__device__ unsigned g_bar[96];
__device__ float g_B[(size_t)N_ * N_]; // compact rw[:, MIS] (stride = M)

__device__ __forceinline__ int ldvi(const int* p) { return *(const volatile int*)p; }

// ---- scoped atomics (no full membars) ----
__device__ __forceinline__ unsigned atom_add_acqrel(unsigned* p, unsigned v)
{
    unsigned old;
    asm volatile("atom.acq_rel.gpu.global.add.u32 %0, [%1], %2;"
                 : "=r"(old) : "l"(p), "r"(v) : "memory");
    return old;
}
__device__ __forceinline__ void red_add_relaxed(unsigned* p, unsigned v)
{
    asm volatile("red.relaxed.gpu.global.add.u32 [%0], %1;" :: "l"(p), "r"(v) : "memory");
}
__device__ __forceinline__ unsigned ld_acquire(const unsigned* p)
{
    unsigned v;
    asm volatile("ld.acquire.gpu.global.b32 %0, [%1];" : "=r"(v) : "l"(p) : "memory");
    return v;
}
__device__ __forceinline__ void st_release(unsigned* p, unsigned v)
{
    asm volatile("st.release.gpu.global.b32 [%0], %1;" :: "l"(p), "r"(v) : "memory");
}
__device__ __forceinline__ void st_relaxed(unsigned* p, unsigned v)
{
    asm volatile("st.relaxed.gpu.global.b32 [%0], %1;" :: "l"(p), "r"(v) : "memory");
}

// ---------------- per-replay init ----------------
__global__ void k_init()
{
    int i = blockIdx.x * blockDim.x + threadIdx.x;
    if (i < N_) { g_degin[i] = 0; g_degout[i] = 0; g_s[i] = 0.f; g_diag[i] = 0.f; g_counts[i] = 0; }
    if (i < 96) g_bar[i] = 0u;
}

// ---------------- grid barrier: acq_rel arrival + release publish + acquire poll ----------------
__device__ __forceinline__ void gridbar(unsigned& ph)
{
    __syncthreads();
    if (threadIdx.x == 0) {
        unsigned a = atom_add_acqrel(&g_bar[0], 1u);
        unsigned rel = 2u * (ph + 1u);
        if (a + 1u == (ph + 1u) * (unsigned)MB_) {
            st_release(&g_bar[32], rel);
        } else {
            while (ld_acquire(&g_bar[32]) < rel) {}
        }
    }
    ph++;
    __syncthreads();
}

// ================= THE fused persistent kernel =================
__global__ void __launch_bounds__(MT_, 1)
k_all(const int* __restrict__ ei, const float* __restrict__ ea,
      const float* __restrict__ x, const int* __restrict__ rank,
      const float* __restrict__ u, float* __restrict__ out, int out_size)
{
    const int bid  = blockIdx.x;
    const int t    = threadIdx.x;
    const int tid  = bid * MT_ + t;
    const int lane = tid & 31;
    const int n    = tid >> 5;            // node == global warp id (2048 warps)

    __shared__ int sMem[2 * N_];
    __shared__ int sFlag;
    int* sA = sMem;
    int* sB = sMem + N_;

    size_t nn = (size_t)N_ * N_;
    float* adjc  = out;
    float* chard = out + nn;
    float* pinv  = out + 2 * nn;
    float* miso  = out + 3 * nn;
    float* xpool = out + 3 * nn + N_;

    unsigned ph = 0;

    // edge tuple cached once (tid == edge id)
    const int   er = ei[tid];
    const int   ec = ei[E_ + tid];
    const float ew = ea[tid];

    // ---- phase 1: degrees, row sums, diag ----
    atomicAdd(&g_degin[ec], 1);
    atomicAdd(&g_degout[er], 1);
    atomicAdd(&g_s[er], ew);
    if (er == ec) atomicAdd(&g_diag[er], ew);
    gridbar(ph);

    // ---- phase 2: block0 scans rowptrs; others: invs/dd + output zero-fill ----
    if (bid == 0) {
        for (int pass = 0; pass < 2; pass++) {
            const int* src = pass ? g_degout : g_degin;
            int* rp  = pass ? g_rpout : g_rpin;
            int* cur = pass ? g_curout : g_curin;
            for (int i = t; i < N_; i += MT_) sA[i] = src[i];
            __syncthreads();
            int* in = sA; int* outp = sB;
            for (int off = 1; off < N_; off <<= 1) {
                for (int i = t; i < N_; i += MT_)
                    outp[i] = in[i] + (i >= off ? in[i - off] : 0);
                __syncthreads();
                int* tmp = in; in = outp; outp = tmp;
            }
            for (int i = t; i < N_; i += MT_) { rp[i + 1] = in[i]; cur[i] = i ? in[i - 1] : 0; }
            if (t == 0) rp[0] = 0;
            __syncthreads();
        }
    } else {
        int i = (bid - 1) * MT_ + t;
        if (i < N_) {
            float s = g_s[i];
            float inv = s > 0.f ? 1.f / s : 1.f;
            g_invs[i] = inv;
            g_dd[i] = 0.5f * (1.f + g_diag[i] * inv);
        }
        float4* o4 = (float4*)out;
        size_t tot4 = (size_t)out_size >> 2;
        for (size_t idx = (size_t)(bid - 1) * MT_ + t; idx < tot4; idx += (size_t)(MB_ - 1) * MT_)
            o4[idx] = make_float4(0.f, 0.f, 0.f, 0.f);
    }
    gridbar(ph);

    // ---- phase 3: fill CSC/CSR + init g_a ----
    {
        int p = atomicAdd(&g_curin[ec], 1);  g_cscsrc[p] = er;
        int q = atomicAdd(&g_curout[er], 1); g_csrdst[q] = ec; g_csrw[q] = 0.5f * ew * g_invs[er];
        if (tid < N_) g_a[tid] = rank[tid];
    }
    gridbar(ph);

    // ---- k-hop MIS: 1 warp/node, reg-cached in-list, reg-carried state ----
    const int beg = g_rpin[n], end = g_rpin[n + 1];
    const int src = (lane < end - beg) ? g_cscsrc[beg + lane] : -1;
    const int rk  = rank[n];
    int misreg = 0;
    int areg   = rk;

    for (int iter = 0; iter < N_; iter++) {
        // hop A: min-prop g_a -> g_bb
        int m1 = areg;
        if (src >= 0) m1 = min(m1, ldvi(&g_a[src]));
        for (int e = beg + 32 + lane; e < end; e += 32) m1 = min(m1, ldvi(&g_a[g_cscsrc[e]]));
        m1 = __reduce_min_sync(0xffffffffu, m1);
        if (lane == 0) g_bb[n] = m1;
        gridbar(ph);

        // hop B: min-prop g_bb -> local; mis update -> g_mka
        int m2 = m1;
        if (src >= 0) m2 = min(m2, ldvi(&g_bb[src]));
        for (int e = beg + 32 + lane; e < end; e += 32) m2 = min(m2, ldvi(&g_bb[g_cscsrc[e]]));
        m2 = __reduce_min_sync(0xffffffffu, m2);
        misreg |= (rk == m2) ? 1 : 0;
        if (lane == 0) g_mka[n] = misreg;
        gridbar(ph);

        // hop C: or-prop g_mka -> g_mkb
        int o1 = misreg;
        if (src >= 0) o1 = max(o1, ldvi(&g_mka[src]));
        for (int e = beg + 32 + lane; e < end; e += 32) o1 = max(o1, ldvi(&g_mka[g_cscsrc[e]]));
        o1 = __reduce_max_sync(0xffffffffu, o1);
        if (lane == 0) g_mkb[n] = o1;
        gridbar(ph);

        // hop D: or-prop g_mkb -> local; finalize; barrier with embedded flag
        int o2 = o1;
        if (src >= 0) o2 = max(o2, ldvi(&g_mkb[src]));
        for (int e = beg + 32 + lane; e < end; e += 32) o2 = max(o2, ldvi(&g_mkb[g_cscsrc[e]]));
        o2 = __reduce_max_sync(0xffffffffu, o2);
        int mask = o2 > 0;
        areg = mask ? N_ : rk;
        if (lane == 0) g_a[n] = areg;
        int nm = (lane == 0 && !mask) ? 1 : 0;
        int any = __syncthreads_count(nm);
        int parity = iter & 1;
        if (t == 0) {
            if (any) red_add_relaxed(&g_bar[64 + parity], 1u);
            unsigned a = atom_add_acqrel(&g_bar[0], 1u);
            unsigned rel = 2u * (ph + 1u);
            unsigned flag;
            if (a + 1u == (ph + 1u) * (unsigned)MB_) {
                unsigned s = ld_acquire(&g_bar[64 + parity]);
                st_relaxed(&g_bar[64 + (parity ^ 1)], 0u);
                flag = s ? 1u : 0u;
                st_release(&g_bar[32], rel + flag);
            } else {
                unsigned v;
                while ((v = ld_acquire(&g_bar[32])) < rel) {}
                flag = v & 1u;
            }
            sFlag = (int)flag;
        }
        ph++;
        __syncthreads();
        if (sFlag == 0) break;
    }
    // g_mka holds the final MIS

    // ---- compact (block 0) -> colmap/qlist/M ----
    if (bid == 0) {
        for (int i = t; i < N_; i += MT_) sA[i] = ldvi(&g_mka[i]);
        __syncthreads();
        int* in = sA; int* outp = sB;
        for (int off = 1; off < N_; off <<= 1) {
            for (int i = t; i < N_; i += MT_)
                outp[i] = in[i] + (i >= off ? in[i - off] : 0);
            __syncthreads();
            int* tmp = in; in = outp; outp = tmp;
        }
        for (int i = t; i < N_; i += MT_) {
            if (ldvi(&g_mka[i])) { int p = in[i] - 1; g_colmap[i] = p; g_qlist[p] = i; }
            else g_colmap[i] = -1;
        }
        if (t == 0) g_M = in[N_ - 1];
    }
    gridbar(ph);

    if (t == 0) sFlag = ldvi(&g_M);
    __syncthreads();
    const int M = sFlag;

    // ---- build B = rw[:, MIS]: warp-per-row, NO zeroing, NO atomics ----
    {
        int r = n;
        int rb = g_rpout[r], re2 = g_rpout[r + 1];
        int cmr = g_colmap[r];
        float ddr = g_dd[r];
        for (int m0 = 0; m0 < M; m0 += 32) {
            int m = m0 + lane;
            float acc = 0.f;
            for (int e = rb; e < re2; e++) {
                int cm = g_colmap[g_csrdst[e]];    // uniform-address broadcast loads
                float w = g_csrw[e];
                if (cm == m) acc += w;
            }
            if (cmr == m) acc += ddr;
            if (m < M) g_B[(size_t)r * M + m] = acc;
        }
    }
    gridbar(ph);

    // ---- SpMM c = rw @ B (warp per row) + fused Gumbel argmax + counts ----
    {
        int i = n;
        int rb = g_rpout[i], re2 = g_rpout[i + 1];
        float dd = g_dd[i];
        const float* ui = u + (size_t)i * N_;
        float best = -INFINITY; int bq = 0x7FFFFFFF; int bm = 0;
        for (int m0 = 0; m0 < M; m0 += 32) {
            int m = m0 + lane;
            if (m < M) {
                float acc = dd * g_B[(size_t)i * M + m];
                for (int e = rb; e < re2; e++)
                    acc += g_csrw[e] * g_B[(size_t)g_csrdst[e] * M + m];
                if (acc > 0.f) {
                    int q = g_qlist[m];
                    float uu = ui[q];
                    float gum = -logf(-logf(uu + 1e-20f) + 1e-20f);
                    float lg = logf(fmaxf(acc, 1e-30f)) + gum;
                    if (lg > best || (lg == best && q < bq)) { best = lg; bq = q; bm = m; }
                }
            }
        }
        for (int o = 16; o > 0; o >>= 1) {
            float v  = __shfl_xor_sync(0xffffffffu, best, o);
            int   q  = __shfl_xor_sync(0xffffffffu, bq, o);
            int   mm = __shfl_xor_sync(0xffffffffu, bm, o);
            if (v > best || (v == best && q < bq)) { best = v; bq = q; bm = mm; }
        }
        if (lane == 0) {
            int cm, cl;
            if (bq == 0x7FFFFFFF) { cm = M; cl = 0; }
            else { cm = bm; cl = bq; }
            g_clustc[i]  = cm;
            g_cluster[i] = cl;
            atomicAdd(&g_counts[cl], 1);
        }
    }
    gridbar(ph);

    // ---- post: miso/chard/pinv + adj_c (smem-aggregated) + x_pool ----
    if (tid < N_) {
        int i = tid;
        miso[i] = g_mka[i] ? 1.f : 0.f;
        int c = g_cluster[i];
        chard[(size_t)i * N_ + c] = 1.f;
        pinv[(size_t)c * N_ + i] = 1.f / (float)g_counts[c];
    }

    {
        const int Mp1 = M + 1;                   // slot M = fallback cluster (node 0)
        if (Mp1 * Mp1 <= 2 * N_) {
            float* sbuf = (float*)sMem;
            for (int i2 = t; i2 < Mp1 * Mp1; i2 += MT_) sbuf[i2] = 0.f;
            __syncthreads();
            atomicAdd(&sbuf[g_clustc[er] * Mp1 + g_clustc[ec]], ew);
            __syncthreads();
            for (int i2 = t; i2 < Mp1 * Mp1; i2 += MT_) {
                float v = sbuf[i2];
                if (v != 0.f) {
                    int m1 = i2 / Mp1, m2 = i2 % Mp1;
                    int r = (m1 < M) ? g_qlist[m1] : 0;
                    int c = (m2 < M) ? g_qlist[m2] : 0;
                    atomicAdd(&adjc[(size_t)r * N_ + c], v);
                }
            }
        } else {
            atomicAdd(&adjc[(size_t)g_cluster[er] * N_ + g_cluster[ec]], ew);
        }
    }

    for (int idx = tid; idx < N_ * D_; idx += NT_) {
        int i = idx >> 9, d = idx & (D_ - 1);
        int c = g_cluster[i];
        float invc = 1.f / (float)g_counts[c];
        atomicAdd(&xpool[(size_t)c * D_ + d], x[idx] * invc);
    }
}

// ---------------- launch ----------------
extern "C" void kernel_launch(void* const* d_in, const int* in_sizes, int n_in,
                              void* d_out, int out_size)
{
    const int*   ei   = (const int*)d_in[0];     // edge_index [2, E]
    const float* ea   = (const float*)d_in[1];   // edge_attr  [E]
    const float* x    = (const float*)d_in[2];   // x          [N, D]
    const int*   rank = (const int*)d_in[3];     // rank       [N]
    const float* u    = (const float*)d_in[4];   // u          [N, N]

    (void)in_sizes; (void)n_in;

    k_init<<<8, 256>>>();
    k_all <<<MB_, MT_>>>(ei, ea, x, rank, u, (float*)d_out, out_size);
}

// round 9
// speedup vs baseline: 1.2393x; 1.0379x over previous
#include <cuda_runtime.h>
#include <math.h>

#define N_ 2048
#define E_ 65536
#define D_ 512

#define MB_ 128                 // persistent blocks (all co-resident on 148 SMs)
#define MT_ 512                 // threads/block
#define NT_ (MB_ * MT_)         // 65536 threads == E_; 2048 warps == N_ nodes

// ---------------- static device scratch (no allocations allowed) ----------------
__device__ int   g_degin[N_], g_degout[N_];
__device__ int   g_rpin[N_ + 1], g_rpout[N_ + 1];
__device__ int   g_curin[N_], g_curout[N_];
__device__ int   g_cscsrc[E_];        // CSC: senders grouped by receiver
__device__ int   g_csrdst[E_];        // CSR: dst grouped by src
__device__ float g_csrw[E_];          // prescaled 0.5*w/s_row
__device__ float g_s[N_], g_invs[N_], g_dd[N_], g_diag[N_];
__device__ int   g_a[N_], g_bb[N_], g_mka[N_];
__device__ int   g_qlist[N_], g_colmap[N_];
__device__ int   g_M;
__device__ int   g_cluster[N_];       // cluster id (original node index q)
__device__ int   g_clustc[N_];        // compact cluster index (M = fallback)
__device__ int   g_counts[N_];
// barrier words on separate 128B lines: [0]=cnt, [32]=release, [64/65]=strag parity
__device__ unsigned g_bar[96];
__device__ float g_B[(size_t)N_ * N_]; // compact rw[:, MIS] (stride = M)

__device__ __forceinline__ int ldvi(const int* p) { return *(const volatile int*)p; }

// ---- scoped atomics (no full membars) ----
__device__ __forceinline__ unsigned atom_add_acqrel(unsigned* p, unsigned v)
{
    unsigned old;
    asm volatile("atom.acq_rel.gpu.global.add.u32 %0, [%1], %2;"
                 : "=r"(old) : "l"(p), "r"(v) : "memory");
    return old;
}
__device__ __forceinline__ void red_add_relaxed(unsigned* p, unsigned v)
{
    asm volatile("red.relaxed.gpu.global.add.u32 [%0], %1;" :: "l"(p), "r"(v) : "memory");
}
__device__ __forceinline__ unsigned ld_acquire(const unsigned* p)
{
    unsigned v;
    asm volatile("ld.acquire.gpu.global.b32 %0, [%1];" : "=r"(v) : "l"(p) : "memory");
    return v;
}
__device__ __forceinline__ void st_release(unsigned* p, unsigned v)
{
    asm volatile("st.release.gpu.global.b32 [%0], %1;" :: "l"(p), "r"(v) : "memory");
}
__device__ __forceinline__ void st_relaxed(unsigned* p, unsigned v)
{
    asm volatile("st.relaxed.gpu.global.b32 [%0], %1;" :: "l"(p), "r"(v) : "memory");
}

// ---------------- per-replay init ----------------
__global__ void k_init()
{
    int i = blockIdx.x * blockDim.x + threadIdx.x;
    if (i < N_) { g_degin[i] = 0; g_degout[i] = 0; g_s[i] = 0.f; g_diag[i] = 0.f; g_counts[i] = 0; }
    if (i < 96) g_bar[i] = 0u;
}

// ---------------- grid barrier: acq_rel arrival + release publish + acquire poll ----------------
__device__ __forceinline__ void gridbar(unsigned& ph)
{
    __syncthreads();
    if (threadIdx.x == 0) {
        unsigned a = atom_add_acqrel(&g_bar[0], 1u);
        unsigned rel = 2u * (ph + 1u);
        if (a + 1u == (ph + 1u) * (unsigned)MB_) {
            st_release(&g_bar[32], rel);
        } else {
            while (ld_acquire(&g_bar[32]) < rel) {}
        }
    }
    ph++;
    __syncthreads();
}

// ================= THE fused persistent kernel =================
__global__ void __launch_bounds__(MT_, 1)
k_all(const int* __restrict__ ei, const float* __restrict__ ea,
      const float* __restrict__ x, const int* __restrict__ rank,
      const float* __restrict__ u, float* __restrict__ out, int out_size)
{
    const int bid  = blockIdx.x;
    const int t    = threadIdx.x;
    const int tid  = bid * MT_ + t;
    const int lane = tid & 31;
    const int n    = tid >> 5;            // node == global warp id (2048 warps)

    __shared__ int sMem[2 * N_];
    __shared__ int sFlag;
    int* sA = sMem;
    int* sB = sMem + N_;

    size_t nn = (size_t)N_ * N_;
    float* adjc  = out;
    float* chard = out + nn;
    float* pinv  = out + 2 * nn;
    float* miso  = out + 3 * nn;
    float* xpool = out + 3 * nn + N_;

    unsigned ph = 0;

    // edge tuple cached once (tid == edge id)
    const int   er = ei[tid];
    const int   ec = ei[E_ + tid];
    const float ew = ea[tid];

    // ---- phase 1: degrees, row sums, diag ----
    atomicAdd(&g_degin[ec], 1);
    atomicAdd(&g_degout[er], 1);
    atomicAdd(&g_s[er], ew);
    if (er == ec) atomicAdd(&g_diag[er], ew);
    gridbar(ph);

    // ---- phase 2: block0 scans rowptrs; others: invs/dd + output zero-fill ----
    if (bid == 0) {
        for (int pass = 0; pass < 2; pass++) {
            const int* src = pass ? g_degout : g_degin;
            int* rp  = pass ? g_rpout : g_rpin;
            int* cur = pass ? g_curout : g_curin;
            for (int i = t; i < N_; i += MT_) sA[i] = src[i];
            __syncthreads();
            int* in = sA; int* outp = sB;
            for (int off = 1; off < N_; off <<= 1) {
                for (int i = t; i < N_; i += MT_)
                    outp[i] = in[i] + (i >= off ? in[i - off] : 0);
                __syncthreads();
                int* tmp = in; in = outp; outp = tmp;
            }
            for (int i = t; i < N_; i += MT_) { rp[i + 1] = in[i]; cur[i] = i ? in[i - 1] : 0; }
            if (t == 0) rp[0] = 0;
            __syncthreads();
        }
    } else {
        int i = (bid - 1) * MT_ + t;
        if (i < N_) {
            float s = g_s[i];
            float inv = s > 0.f ? 1.f / s : 1.f;
            g_invs[i] = inv;
            g_dd[i] = 0.5f * (1.f + g_diag[i] * inv);
        }
        float4* o4 = (float4*)out;
        size_t tot4 = (size_t)out_size >> 2;
        for (size_t idx = (size_t)(bid - 1) * MT_ + t; idx < tot4; idx += (size_t)(MB_ - 1) * MT_)
            o4[idx] = make_float4(0.f, 0.f, 0.f, 0.f);
    }
    gridbar(ph);

    // ---- phase 3: fill CSC/CSR + init MIS state ----
    {
        int p = atomicAdd(&g_curin[ec], 1);  g_cscsrc[p] = er;
        int q = atomicAdd(&g_curout[er], 1); g_csrdst[q] = ec; g_csrw[q] = 0.5f * ew * g_invs[er];
        if (tid < N_) { g_a[tid] = rank[tid]; g_mka[tid] = 0; }
    }
    gridbar(ph);

    // ---- k-hop MIS: fused single-propagation scheme, 2 barriers/iteration ----
    // val encoding: -1 = MIS member, rank = undecided, N = covered (non-MIS, near MIS)
    // closed 2-hop min m:  m == rank -> join (true greedy local min among undecided)
    //                      m == -1   -> covered
    // Confluent to the reference's greedy fixed point; mis set is identical.
    const int beg = g_rpin[n], end = g_rpin[n + 1];
    const int src = (lane < end - beg) ? g_cscsrc[beg + lane] : -1;
    const int rk  = rank[n];
    int misreg = 0;
    int areg   = rk;

    for (int iter = 0; iter < N_; iter++) {
        // hop A: closed 1-hop min of val -> g_bb
        int m1 = areg;
        if (src >= 0) m1 = min(m1, ldvi(&g_a[src]));
        for (int e = beg + 32 + lane; e < end; e += 32) m1 = min(m1, ldvi(&g_a[g_cscsrc[e]]));
        m1 = __reduce_min_sync(0xffffffffu, m1);
        if (lane == 0) g_bb[n] = m1;
        gridbar(ph);

        // hop B: closed 2-hop min; state update; barrier with embedded straggler flag
        int m2 = m1;
        if (src >= 0) m2 = min(m2, ldvi(&g_bb[src]));
        for (int e = beg + 32 + lane; e < end; e += 32) m2 = min(m2, ldvi(&g_bb[g_cscsrc[e]]));
        m2 = __reduce_min_sync(0xffffffffu, m2);
        int joined  = (m2 == rk);          // impossible if already mis (val=-1 => m2=-1)
        misreg |= joined;
        int covered = (m2 == -1);
        areg = misreg ? -1 : (covered ? N_ : rk);
        if (lane == 0) {
            g_a[n] = areg;
            if (joined) g_mka[n] = 1;
        }
        int straggler = (lane == 0 && !misreg && !covered) ? 1 : 0;
        int any = __syncthreads_count(straggler);
        int parity = iter & 1;
        if (t == 0) {
            if (any) red_add_relaxed(&g_bar[64 + parity], 1u);
            unsigned a = atom_add_acqrel(&g_bar[0], 1u);
            unsigned rel = 2u * (ph + 1u);
            unsigned flag;
            if (a + 1u == (ph + 1u) * (unsigned)MB_) {
                unsigned s = ld_acquire(&g_bar[64 + parity]);
                st_relaxed(&g_bar[64 + (parity ^ 1)], 0u);
                flag = s ? 1u : 0u;
                st_release(&g_bar[32], rel + flag);
            } else {
                unsigned v;
                while ((v = ld_acquire(&g_bar[32])) < rel) {}
                flag = v & 1u;
            }
            sFlag = (int)flag;
        }
        ph++;
        __syncthreads();
        if (sFlag == 0) break;
    }
    // g_mka holds the final MIS

    // ---- compact (block 0) -> colmap/qlist/M ----
    if (bid == 0) {
        for (int i = t; i < N_; i += MT_) sA[i] = ldvi(&g_mka[i]);
        __syncthreads();
        int* in = sA; int* outp = sB;
        for (int off = 1; off < N_; off <<= 1) {
            for (int i = t; i < N_; i += MT_)
                outp[i] = in[i] + (i >= off ? in[i - off] : 0);
            __syncthreads();
            int* tmp = in; in = outp; outp = tmp;
        }
        for (int i = t; i < N_; i += MT_) {
            if (ldvi(&g_mka[i])) { int p = in[i] - 1; g_colmap[i] = p; g_qlist[p] = i; }
            else g_colmap[i] = -1;
        }
        if (t == 0) g_M = in[N_ - 1];
    }
    gridbar(ph);

    if (t == 0) sFlag = ldvi(&g_M);
    __syncthreads();
    const int M = sFlag;

    // ---- build B = rw[:, MIS]: warp-per-row, NO zeroing, NO atomics ----
    {
        int r = n;
        int rb = g_rpout[r], re2 = g_rpout[r + 1];
        int cmr = g_colmap[r];
        float ddr = g_dd[r];
        for (int m0 = 0; m0 < M; m0 += 32) {
            int m = m0 + lane;
            float acc = 0.f;
            for (int e = rb; e < re2; e++) {
                int cm = g_colmap[g_csrdst[e]];    // uniform-address broadcast loads
                float w = g_csrw[e];
                if (cm == m) acc += w;
            }
            if (cmr == m) acc += ddr;
            if (m < M) g_B[(size_t)r * M + m] = acc;
        }
    }
    gridbar(ph);

    // ---- SpMM c = rw @ B (warp per row) + fused Gumbel argmax + counts ----
    {
        int i = n;
        int rb = g_rpout[i], re2 = g_rpout[i + 1];
        float dd = g_dd[i];
        const float* ui = u + (size_t)i * N_;
        float best = -INFINITY; int bq = 0x7FFFFFFF; int bm = 0;
        for (int m0 = 0; m0 < M; m0 += 32) {
            int m = m0 + lane;
            if (m < M) {
                float acc = dd * g_B[(size_t)i * M + m];
                for (int e = rb; e < re2; e++)
                    acc += g_csrw[e] * g_B[(size_t)g_csrdst[e] * M + m];
                if (acc > 0.f) {
                    int q = g_qlist[m];
                    float uu = ui[q];
                    float gum = -logf(-logf(uu + 1e-20f) + 1e-20f);
                    float lg = logf(fmaxf(acc, 1e-30f)) + gum;
                    if (lg > best || (lg == best && q < bq)) { best = lg; bq = q; bm = m; }
                }
            }
        }
        for (int o = 16; o > 0; o >>= 1) {
            float v  = __shfl_xor_sync(0xffffffffu, best, o);
            int   q  = __shfl_xor_sync(0xffffffffu, bq, o);
            int   mm = __shfl_xor_sync(0xffffffffu, bm, o);
            if (v > best || (v == best && q < bq)) { best = v; bq = q; bm = mm; }
        }
        if (lane == 0) {
            int cm, cl;
            if (bq == 0x7FFFFFFF) { cm = M; cl = 0; }
            else { cm = bm; cl = bq; }
            g_clustc[i]  = cm;
            g_cluster[i] = cl;
            atomicAdd(&g_counts[cl], 1);
        }
    }
    gridbar(ph);

    // ---- post: miso/chard/pinv + adj_c (smem-aggregated) + x_pool ----
    if (tid < N_) {
        int i = tid;
        miso[i] = g_mka[i] ? 1.f : 0.f;
        int c = g_cluster[i];
        chard[(size_t)i * N_ + c] = 1.f;
        pinv[(size_t)c * N_ + i] = 1.f / (float)g_counts[c];
    }

    {
        const int Mp1 = M + 1;                   // slot M = fallback cluster (node 0)
        if (Mp1 * Mp1 <= 2 * N_) {
            float* sbuf = (float*)sMem;
            for (int i2 = t; i2 < Mp1 * Mp1; i2 += MT_) sbuf[i2] = 0.f;
            __syncthreads();
            atomicAdd(&sbuf[g_clustc[er] * Mp1 + g_clustc[ec]], ew);
            __syncthreads();
            for (int i2 = t; i2 < Mp1 * Mp1; i2 += MT_) {
                float v = sbuf[i2];
                if (v != 0.f) {
                    int m1 = i2 / Mp1, m2 = i2 % Mp1;
                    int r = (m1 < M) ? g_qlist[m1] : 0;
                    int c = (m2 < M) ? g_qlist[m2] : 0;
                    atomicAdd(&adjc[(size_t)r * N_ + c], v);
                }
            }
        } else {
            atomicAdd(&adjc[(size_t)g_cluster[er] * N_ + g_cluster[ec]], ew);
        }
    }

    for (int idx = tid; idx < N_ * D_; idx += NT_) {
        int i = idx >> 9, d = idx & (D_ - 1);
        int c = g_cluster[i];
        float invc = 1.f / (float)g_counts[c];
        atomicAdd(&xpool[(size_t)c * D_ + d], x[idx] * invc);
    }
}

// ---------------- launch ----------------
extern "C" void kernel_launch(void* const* d_in, const int* in_sizes, int n_in,
                              void* d_out, int out_size)
{
    const int*   ei   = (const int*)d_in[0];     // edge_index [2, E]
    const float* ea   = (const float*)d_in[1];   // edge_attr  [E]
    const float* x    = (const float*)d_in[2];   // x          [N, D]
    const int*   rank = (const int*)d_in[3];     // rank       [N]
    const float* u    = (const float*)d_in[4];   // u          [N, N]

    (void)in_sizes; (void)n_in;

    k_init<<<8, 256>>>();
    k_all <<<MB_, MT_>>>(ei, ea, x, rank, u, (float*)d_out, out_size);
}

// round 10
// speedup vs baseline: 1.5480x; 1.2491x over previous
#include <cuda_runtime.h>
#include <math.h>

#define N_ 2048
#define E_ 65536
#define D_ 512

#define MB_ 128                 // persistent blocks
#define MT_ 512                 // threads/block
#define NT_ (MB_ * MT_)         // 65536 threads == E_
#define MISB_ 32                // blocks participating in the MIS loop

// ---------------- static device scratch (no allocations allowed) ----------------
__device__ int   g_degin[N_], g_degout[N_];
__device__ int   g_rpin[N_ + 1], g_rpout[N_ + 1];
__device__ int   g_curin[N_], g_curout[N_];
__device__ int   g_cscsrc[E_];        // CSC: senders grouped by receiver
__device__ int   g_csrdst[E_];        // CSR: dst grouped by src
__device__ float g_csrw[E_];          // prescaled 0.5*w/s_row
__device__ float g_s[N_], g_invs[N_], g_dd[N_], g_diag[N_];
__device__ __align__(16) int g_a[N_];
__device__ __align__(16) int g_bb[N_];
__device__ int   g_mka[N_];
__device__ int   g_qlist[N_], g_colmap[N_];
__device__ int   g_M;
__device__ int   g_cluster[N_];       // cluster id (original node index q)
__device__ int   g_clustc[N_];        // compact cluster index (M = fallback)
__device__ int   g_counts[N_];
// barrier words, each on its own 128B line:
// [0]=main cnt, [32]=main rel, [64]/[65]=strag parity, [96]=sub cnt, [128]=sub rel, [160]=mis_done
__device__ unsigned g_bar[192];
__device__ float g_B[(size_t)N_ * N_]; // compact rw[:, MIS] (stride = M)

__device__ __forceinline__ int ldvi(const int* p) { return *(const volatile int*)p; }

// ---- scoped atomics (no full membars) ----
__device__ __forceinline__ unsigned atom_add_acqrel(unsigned* p, unsigned v)
{
    unsigned old;
    asm volatile("atom.acq_rel.gpu.global.add.u32 %0, [%1], %2;"
                 : "=r"(old) : "l"(p), "r"(v) : "memory");
    return old;
}
__device__ __forceinline__ void red_add_relaxed(unsigned* p, unsigned v)
{
    asm volatile("red.relaxed.gpu.global.add.u32 [%0], %1;" :: "l"(p), "r"(v) : "memory");
}
__device__ __forceinline__ unsigned ld_acquire(const unsigned* p)
{
    unsigned v;
    asm volatile("ld.acquire.gpu.global.b32 %0, [%1];" : "=r"(v) : "l"(p) : "memory");
    return v;
}
__device__ __forceinline__ void st_release(unsigned* p, unsigned v)
{
    asm volatile("st.release.gpu.global.b32 [%0], %1;" :: "l"(p), "r"(v) : "memory");
}
__device__ __forceinline__ void st_relaxed(unsigned* p, unsigned v)
{
    asm volatile("st.relaxed.gpu.global.b32 [%0], %1;" :: "l"(p), "r"(v) : "memory");
}

// ---------------- per-replay init ----------------
__global__ void k_init()
{
    int i = blockIdx.x * blockDim.x + threadIdx.x;
    if (i < N_) { g_degin[i] = 0; g_degout[i] = 0; g_s[i] = 0.f; g_diag[i] = 0.f; g_counts[i] = 0; }
    if (i < 192) g_bar[i] = 0u;
}

// ---------------- full-grid barrier ----------------
__device__ __forceinline__ void gridbar(unsigned& ph)
{
    __syncthreads();
    if (threadIdx.x == 0) {
        unsigned a = atom_add_acqrel(&g_bar[0], 1u);
        unsigned rel = 2u * (ph + 1u);
        if (a + 1u == (ph + 1u) * (unsigned)MB_) {
            st_release(&g_bar[32], rel);
        } else {
            while (ld_acquire(&g_bar[32]) < rel) {}
        }
    }
    ph++;
    __syncthreads();
}

// ---------------- 32-block sub-barrier (plain) ----------------
__device__ __forceinline__ void subbar(unsigned& sph)
{
    __syncthreads();
    if (threadIdx.x == 0) {
        unsigned a = atom_add_acqrel(&g_bar[96], 1u);
        unsigned rel = 2u * (sph + 1u);
        if (a + 1u == (sph + 1u) * (unsigned)MISB_) {
            st_release(&g_bar[128], rel);
        } else {
            while (ld_acquire(&g_bar[128]) < rel) {}
        }
    }
    sph++;
    __syncthreads();
}

// ================= THE fused persistent kernel =================
__global__ void __launch_bounds__(MT_, 1)
k_all(const int* __restrict__ ei, const float* __restrict__ ea,
      const float* __restrict__ x, const int* __restrict__ rank,
      const float* __restrict__ u, float* __restrict__ out, int out_size)
{
    const int bid  = blockIdx.x;
    const int t    = threadIdx.x;
    const int tid  = bid * MT_ + t;
    const int lane = tid & 31;
    const int n    = tid >> 5;            // node == global warp id (2048 warps)

    __shared__ __align__(16) int sMem[2 * N_];
    __shared__ int sFlag;
    int* sA = sMem;
    int* sB = sMem + N_;

    size_t nn = (size_t)N_ * N_;
    float* adjc  = out;
    float* chard = out + nn;
    float* pinv  = out + 2 * nn;
    float* miso  = out + 3 * nn;
    float* xpool = out + 3 * nn + N_;

    unsigned ph = 0;

    // edge tuple cached once (tid == edge id)
    const int   er = ei[tid];
    const int   ec = ei[E_ + tid];
    const float ew = ea[tid];

    // ---- phase 1: degrees, row sums, diag ----
    atomicAdd(&g_degin[ec], 1);
    atomicAdd(&g_degout[er], 1);
    atomicAdd(&g_s[er], ew);
    if (er == ec) atomicAdd(&g_diag[er], ew);
    gridbar(ph);

    // ---- phase 2: block0 scans rowptrs; others: invs/dd + output zero-fill ----
    if (bid == 0) {
        for (int pass = 0; pass < 2; pass++) {
            const int* src = pass ? g_degout : g_degin;
            int* rp  = pass ? g_rpout : g_rpin;
            int* cur = pass ? g_curout : g_curin;
            for (int i = t; i < N_; i += MT_) sA[i] = src[i];
            __syncthreads();
            int* in = sA; int* outp = sB;
            for (int off = 1; off < N_; off <<= 1) {
                for (int i = t; i < N_; i += MT_)
                    outp[i] = in[i] + (i >= off ? in[i - off] : 0);
                __syncthreads();
                int* tmp = in; in = outp; outp = tmp;
            }
            for (int i = t; i < N_; i += MT_) { rp[i + 1] = in[i]; cur[i] = i ? in[i - 1] : 0; }
            if (t == 0) rp[0] = 0;
            __syncthreads();
        }
    } else {
        int i = (bid - 1) * MT_ + t;
        if (i < N_) {
            float s = g_s[i];
            float inv = s > 0.f ? 1.f / s : 1.f;
            g_invs[i] = inv;
            g_dd[i] = 0.5f * (1.f + g_diag[i] * inv);
        }
        float4* o4 = (float4*)out;
        size_t tot4 = (size_t)out_size >> 2;
        for (size_t idx = (size_t)(bid - 1) * MT_ + t; idx < tot4; idx += (size_t)(MB_ - 1) * MT_)
            o4[idx] = make_float4(0.f, 0.f, 0.f, 0.f);
    }
    gridbar(ph);

    // ---- phase 3: fill CSC/CSR + init MIS state ----
    {
        int p = atomicAdd(&g_curin[ec], 1);  g_cscsrc[p] = er;
        int q = atomicAdd(&g_curout[er], 1); g_csrdst[q] = ec; g_csrw[q] = 0.5f * ew * g_invs[er];
        if (tid < N_) { g_a[tid] = rank[tid]; g_mka[tid] = 0; }
    }
    gridbar(ph);

    // ---- k-hop MIS on 32 blocks: 4 nodes/warp, smem-staged state, sub-barrier ----
    // val encoding: -1 = MIS, rank = undecided, N = covered.
    if (bid < MISB_) {
        unsigned sph = 0;
        const int w  = t >> 5;
        const int nb = (bid * 16 + w) * 4;   // 4 consecutive nodes per warp
        int rk4[4], src4[4], beg4[4], end4[4], areg4[4], mis4[4];
#pragma unroll
        for (int j = 0; j < 4; j++) {
            int nd = nb + j;
            rk4[j]  = rank[nd];
            beg4[j] = g_rpin[nd];
            end4[j] = g_rpin[nd + 1];
            src4[j] = (lane < end4[j] - beg4[j]) ? g_cscsrc[beg4[j] + lane] : -1;
            areg4[j] = rk4[j];
            mis4[j]  = 0;
        }

        for (int iter = 0; iter < N_; iter++) {
            // hop A: stage g_a, closed 1-hop min -> g_bb
            ((int4*)sA)[t] = ((const int4*)g_a)[t];
            __syncthreads();
            int m1[4];
#pragma unroll
            for (int j = 0; j < 4; j++) {
                int m = areg4[j];
                if (src4[j] >= 0) m = min(m, sA[src4[j]]);
                for (int e = beg4[j] + 32 + lane; e < end4[j]; e += 32) m = min(m, sA[g_cscsrc[e]]);
                m1[j] = __reduce_min_sync(0xffffffffu, m);
            }
            if (lane == 0) *(int4*)&g_bb[nb] = make_int4(m1[0], m1[1], m1[2], m1[3]);
            subbar(sph);

            // hop B: stage g_bb, closed 2-hop min; join/cover; publish; flagged sub-barrier
            ((int4*)sA)[t] = ((const int4*)g_bb)[t];
            __syncthreads();
            int undec = 0;
            int a4[4];
#pragma unroll
            for (int j = 0; j < 4; j++) {
                int m = m1[j];
                if (src4[j] >= 0) m = min(m, sA[src4[j]]);
                for (int e = beg4[j] + 32 + lane; e < end4[j]; e += 32) m = min(m, sA[g_cscsrc[e]]);
                m = __reduce_min_sync(0xffffffffu, m);
                int joined  = (m == rk4[j]);
                mis4[j] |= joined;
                int covered = (m == -1);
                areg4[j] = mis4[j] ? -1 : (covered ? N_ : rk4[j]);
                a4[j] = areg4[j];
                if (lane == 0 && joined) g_mka[nb + j] = 1;
                undec |= (!mis4[j] && !covered) ? 1 : 0;
            }
            if (lane == 0) *(int4*)&g_a[nb] = make_int4(a4[0], a4[1], a4[2], a4[3]);
            int strag = (lane == 0 && undec) ? 1 : 0;
            int any = __syncthreads_count(strag);
            int parity = iter & 1;
            if (t == 0) {
                if (any) red_add_relaxed(&g_bar[64 + parity], 1u);
                unsigned a = atom_add_acqrel(&g_bar[96], 1u);
                unsigned rel = 2u * (sph + 1u);
                unsigned flag;
                if (a + 1u == (sph + 1u) * (unsigned)MISB_) {
                    unsigned s = ld_acquire(&g_bar[64 + parity]);
                    st_relaxed(&g_bar[64 + (parity ^ 1)], 0u);
                    flag = s ? 1u : 0u;
                    st_release(&g_bar[128], rel + flag);
                } else {
                    unsigned v;
                    while ((v = ld_acquire(&g_bar[128])) < rel) {}
                    flag = v & 1u;
                }
                sFlag = (int)flag;
            }
            sph++;
            __syncthreads();
            if (sFlag == 0) break;
        }
        if (bid == 0 && t == 0) st_release(&g_bar[160], 1u);
    } else {
        // idle blocks: low-traffic wait for MIS completion
        if (t == 0) {
            while (ld_acquire(&g_bar[160]) == 0u) __nanosleep(256);
        }
    }
    gridbar(ph);
    // g_mka holds the final MIS

    // ---- compact (block 0) -> colmap/qlist/M ----
    if (bid == 0) {
        for (int i = t; i < N_; i += MT_) sA[i] = ldvi(&g_mka[i]);
        __syncthreads();
        int* in = sA; int* outp = sB;
        for (int off = 1; off < N_; off <<= 1) {
            for (int i = t; i < N_; i += MT_)
                outp[i] = in[i] + (i >= off ? in[i - off] : 0);
            __syncthreads();
            int* tmp = in; in = outp; outp = tmp;
        }
        for (int i = t; i < N_; i += MT_) {
            if (ldvi(&g_mka[i])) { int p = in[i] - 1; g_colmap[i] = p; g_qlist[p] = i; }
            else g_colmap[i] = -1;
        }
        if (t == 0) g_M = in[N_ - 1];
    }
    gridbar(ph);

    if (t == 0) sFlag = ldvi(&g_M);
    __syncthreads();
    const int M = sFlag;

    // ---- build B = rw[:, MIS]: warp-per-row, NO zeroing, NO atomics ----
    {
        int r = n;
        int rb = g_rpout[r], re2 = g_rpout[r + 1];
        int cmr = g_colmap[r];
        float ddr = g_dd[r];
        for (int m0 = 0; m0 < M; m0 += 32) {
            int m = m0 + lane;
            float acc = 0.f;
            for (int e = rb; e < re2; e++) {
                int cm = g_colmap[g_csrdst[e]];    // uniform-address broadcast loads
                float w2 = g_csrw[e];
                if (cm == m) acc += w2;
            }
            if (cmr == m) acc += ddr;
            if (m < M) g_B[(size_t)r * M + m] = acc;
        }
    }
    gridbar(ph);

    // ---- SpMM c = rw @ B (warp per row) + fused Gumbel argmax + counts ----
    {
        int i = n;
        int rb = g_rpout[i], re2 = g_rpout[i + 1];
        float dd = g_dd[i];
        const float* ui = u + (size_t)i * N_;
        float best = -INFINITY; int bq = 0x7FFFFFFF; int bm = 0;
        for (int m0 = 0; m0 < M; m0 += 32) {
            int m = m0 + lane;
            if (m < M) {
                float acc = dd * g_B[(size_t)i * M + m];
                for (int e = rb; e < re2; e++)
                    acc += g_csrw[e] * g_B[(size_t)g_csrdst[e] * M + m];
                if (acc > 0.f) {
                    int q = g_qlist[m];
                    float uu = ui[q];
                    float gum = -logf(-logf(uu + 1e-20f) + 1e-20f);
                    float lg = logf(fmaxf(acc, 1e-30f)) + gum;
                    if (lg > best || (lg == best && q < bq)) { best = lg; bq = q; bm = m; }
                }
            }
        }
        for (int o = 16; o > 0; o >>= 1) {
            float v  = __shfl_xor_sync(0xffffffffu, best, o);
            int   q  = __shfl_xor_sync(0xffffffffu, bq, o);
            int   mm = __shfl_xor_sync(0xffffffffu, bm, o);
            if (v > best || (v == best && q < bq)) { best = v; bq = q; bm = mm; }
        }
        if (lane == 0) {
            int cm, cl;
            if (bq == 0x7FFFFFFF) { cm = M; cl = 0; }
            else { cm = bm; cl = bq; }
            g_clustc[i]  = cm;
            g_cluster[i] = cl;
            atomicAdd(&g_counts[cl], 1);
        }
    }
    gridbar(ph);

    // ---- post: miso/chard/pinv + adj_c (smem-aggregated) + x_pool ----
    if (tid < N_) {
        int i = tid;
        miso[i] = g_mka[i] ? 1.f : 0.f;
        int c = g_cluster[i];
        chard[(size_t)i * N_ + c] = 1.f;
        pinv[(size_t)c * N_ + i] = 1.f / (float)g_counts[c];
    }

    {
        const int Mp1 = M + 1;                   // slot M = fallback cluster (node 0)
        if (Mp1 * Mp1 <= 2 * N_) {
            float* sbuf = (float*)sMem;
            for (int i2 = t; i2 < Mp1 * Mp1; i2 += MT_) sbuf[i2] = 0.f;
            __syncthreads();
            atomicAdd(&sbuf[g_clustc[er] * Mp1 + g_clustc[ec]], ew);
            __syncthreads();
            for (int i2 = t; i2 < Mp1 * Mp1; i2 += MT_) {
                float v = sbuf[i2];
                if (v != 0.f) {
                    int m1 = i2 / Mp1, m2 = i2 % Mp1;
                    int r = (m1 < M) ? g_qlist[m1] : 0;
                    int c = (m2 < M) ? g_qlist[m2] : 0;
                    atomicAdd(&adjc[(size_t)r * N_ + c], v);
                }
            }
        } else {
            atomicAdd(&adjc[(size_t)g_cluster[er] * N_ + g_cluster[ec]], ew);
        }
    }

    for (int idx = tid; idx < N_ * D_; idx += NT_) {
        int i = idx >> 9, d = idx & (D_ - 1);
        int c = g_cluster[i];
        float invc = 1.f / (float)g_counts[c];
        atomicAdd(&xpool[(size_t)c * D_ + d], x[idx] * invc);
    }
}

// ---------------- launch ----------------
extern "C" void kernel_launch(void* const* d_in, const int* in_sizes, int n_in,
                              void* d_out, int out_size)
{
    const int*   ei   = (const int*)d_in[0];     // edge_index [2, E]
    const float* ea   = (const float*)d_in[1];   // edge_attr  [E]
    const float* x    = (const float*)d_in[2];   // x          [N, D]
    const int*   rank = (const int*)d_in[3];     // rank       [N]
    const float* u    = (const float*)d_in[4];   // u          [N, N]

    (void)in_sizes; (void)n_in;

    k_init<<<8, 256>>>();
    k_all <<<MB_, MT_>>>(ei, ea, x, rank, u, (float*)d_out, out_size);
}